// round 4
// baseline (speedup 1.0000x reference)
#include <cuda_runtime.h>
#include <cuda_bf16.h>
#include <math.h>
#include <stdint.h>

#define BATCH 8
#define SEQLEN 4096
#define DMODEL 512
#define SDIM 64
#define MROWS (BATCH * SEQLEN)          // 32768
#define HIDDEN (2 * DMODEL)             // 1024

// ---------------- scratch (device globals; no allocation allowed) -----------
__device__ float g_xn[(long)MROWS * DMODEL];   // 64 MB
__device__ float g_xB[(long)MROWS * SDIM];     // 8 MB
__device__ float g_hs[(long)MROWS * SDIM];     // 8 MB
__device__ float g_y [(long)MROWS * DMODEL];   // 64 MB
__device__ float g_yn[(long)MROWS * DMODEL];   // 64 MB
__device__ float g_h1[(long)MROWS * HIDDEN];   // 128 MB

// ---------------- LayerNorm over last dim (512), one block per row ----------
__global__ void ln_kernel(const float* __restrict__ x,
                          const float* __restrict__ gamma,
                          const float* __restrict__ beta,
                          float* __restrict__ out) {
    int row = blockIdx.x;
    const float* xr = x + (long)row * DMODEL;
    int t = threadIdx.x;                 // 256 threads, 2 elems each
    float v0 = xr[t], v1 = xr[t + 256];

    __shared__ float red1[8];
    __shared__ float red2[8];

    float s = v0 + v1;
    #pragma unroll
    for (int o = 16; o; o >>= 1) s += __shfl_xor_sync(0xffffffffu, s, o);
    if ((t & 31) == 0) red1[t >> 5] = s;
    __syncthreads();
    float mu = 0.f;
    #pragma unroll
    for (int i = 0; i < 8; i++) mu += red1[i];
    mu *= (1.0f / DMODEL);

    float d0 = v0 - mu, d1 = v1 - mu;
    float ss = d0 * d0 + d1 * d1;
    #pragma unroll
    for (int o = 16; o; o >>= 1) ss += __shfl_xor_sync(0xffffffffu, ss, o);
    if ((t & 31) == 0) red2[t >> 5] = ss;
    __syncthreads();
    float var = 0.f;
    #pragma unroll
    for (int i = 0; i < 8; i++) var += red2[i];
    var *= (1.0f / DMODEL);

    float rstd = rsqrtf(var + 1e-5f);
    float* orow = out + (long)row * DMODEL;
    orow[t]       = d0 * rstd * gamma[t]       + beta[t];
    orow[t + 256] = d1 * rstd * gamma[t + 256] + beta[t + 256];
}

// ---------------- diagonal SSM scan: warp per (b, s), chunked ---------------
// xB, hs layout: [b][l][s] row-major ([MROWS, SDIM])
__global__ void scan_kernel(const float* __restrict__ xB,
                            const float* __restrict__ log_A,
                            const float* __restrict__ log_dt,
                            float* __restrict__ hs) {
    const int CH = SEQLEN / 32;          // 128 timesteps per lane
    int w    = blockIdx.x * 8 + (threadIdx.x >> 5);   // 512 warps total
    int lane = threadIdx.x & 31;
    int b = w >> 6, s = w & 63;

    float dt = expf(log_dt[0]);
    float a  = expf(-expf(log_A[s]) * dt);

    long base = ((long)b * SEQLEN + (long)lane * CH) * SDIM + s;
    const float* in  = xB + base;
    float*       out = hs + base;

    // pass 1: local inclusive scan with h_in = 0
    float h = 0.f;
    #pragma unroll 8
    for (int t = 0; t < CH; t++) {
        h = fmaf(a, h, in[(long)t * SDIM]);
        out[(long)t * SDIM] = h;
    }

    // q = a^CH (CH = 128 = 2^7)
    float q = a;
    #pragma unroll
    for (int i = 0; i < 7; i++) q *= q;

    // Hillis-Steele scan of chunk finals with coefficient q
    float v = h, qd = q;
    #pragma unroll
    for (int off = 1; off < 32; off <<= 1) {
        float u = __shfl_up_sync(0xffffffffu, v, off);
        if (lane >= off) v = fmaf(qd, u, v);
        qd *= qd;
    }
    float carry = __shfl_up_sync(0xffffffffu, v, 1);
    if (lane == 0) carry = 0.f;

    // pass 2: h_t = local_t + carry * a^(t+1)
    if (carry != 0.f) {
        float p = a;
        for (int t = 0; t < CH; t++) {
            out[(long)t * SDIM] = fmaf(carry, p, out[(long)t * SDIM]);
            p *= a;
        }
    }
}

// ---------------- fp32 tiled SGEMM (small GEMMs): out = A @ W (+ epilogue) --
// EPI 0: plain
// EPI 2: acc + res[idx] + res2[idx] * dvec[n]        (y = hsC + x + xn*D)
__device__ __forceinline__ float gelu_exact(float v) {
    return 0.5f * v * (1.0f + erff(v * 0.70710678118654752f));
}

template<int EPI>
__global__ void sgemm64(const float* __restrict__ A,
                        const float* __restrict__ W,
                        const float* __restrict__ bias,
                        const float* __restrict__ res,
                        const float* __restrict__ res2,
                        const float* __restrict__ dvec,
                        float* __restrict__ out,
                        int M, int N, int K) {
    __shared__ float As[16][68];
    __shared__ float Bs[16][68];

    int tid = threadIdx.x;               // 256
    int tx = tid & 15;                   // n-tile
    int ty = tid >> 4;                   // m-tile
    int bm = blockIdx.y * 64, bn = blockIdx.x * 64;

    float acc[4][4] = {};

    int arow = tid >> 2, acol = (tid & 3) * 4;   // A tile: 64x16
    int brow = tid >> 4, bcol = (tid & 15) * 4;  // W tile: 16x64

    const float* Aptr = A + (long)(bm + arow) * K + acol;
    const float* Wptr = W + (long)brow * N + bn + bcol;

    for (int k0 = 0; k0 < K; k0 += 16) {
        float4 av = *(const float4*)Aptr;  Aptr += 16;
        float4 bv = *(const float4*)Wptr;  Wptr += (long)16 * N;
        As[acol + 0][arow] = av.x;
        As[acol + 1][arow] = av.y;
        As[acol + 2][arow] = av.z;
        As[acol + 3][arow] = av.w;
        *(float4*)&Bs[brow][bcol] = bv;
        __syncthreads();
        #pragma unroll
        for (int k = 0; k < 16; k++) {
            float4 a4 = *(const float4*)&As[k][ty * 4];
            float4 b4 = *(const float4*)&Bs[k][tx * 4];
            acc[0][0] = fmaf(a4.x, b4.x, acc[0][0]);
            acc[0][1] = fmaf(a4.x, b4.y, acc[0][1]);
            acc[0][2] = fmaf(a4.x, b4.z, acc[0][2]);
            acc[0][3] = fmaf(a4.x, b4.w, acc[0][3]);
            acc[1][0] = fmaf(a4.y, b4.x, acc[1][0]);
            acc[1][1] = fmaf(a4.y, b4.y, acc[1][1]);
            acc[1][2] = fmaf(a4.y, b4.z, acc[1][2]);
            acc[1][3] = fmaf(a4.y, b4.w, acc[1][3]);
            acc[2][0] = fmaf(a4.z, b4.x, acc[2][0]);
            acc[2][1] = fmaf(a4.z, b4.y, acc[2][1]);
            acc[2][2] = fmaf(a4.z, b4.z, acc[2][2]);
            acc[2][3] = fmaf(a4.z, b4.w, acc[2][3]);
            acc[3][0] = fmaf(a4.w, b4.x, acc[3][0]);
            acc[3][1] = fmaf(a4.w, b4.y, acc[3][1]);
            acc[3][2] = fmaf(a4.w, b4.z, acc[3][2]);
            acc[3][3] = fmaf(a4.w, b4.w, acc[3][3]);
        }
        __syncthreads();
    }

    int m0 = bm + ty * 4, n0 = bn + tx * 4;
    #pragma unroll
    for (int i = 0; i < 4; i++) {
        #pragma unroll
        for (int j = 0; j < 4; j++) {
            float v = acc[i][j];
            long idx = (long)(m0 + i) * N + n0 + j;
            if (EPI == 2) {
                v += res[idx] + res2[idx] * dvec[n0 + j];
            }
            out[idx] = v;
        }
    }
}

// ---------------- tf32 MMA GEMM (MLP GEMMs): out = A @ W (+ epilogue) -------
// EPI 1: gelu(acc + bias[n])
// EPI 3: acc + bias[n] + res[idx]
// Block 128x128, K-chunk 16, 8 warps (2x4), warp tile 64x32, m16n8k8 tf32.
__device__ __forceinline__ uint32_t f2tf(float x) {
    uint32_t r;
    asm("cvt.rna.tf32.f32 %0, %1;" : "=r"(r) : "f"(x));
    return r;
}

__device__ __forceinline__ void mma_tf32(float* c, const uint32_t* a, const uint32_t* b) {
    asm volatile(
        "mma.sync.aligned.m16n8k8.row.col.f32.tf32.tf32.f32 "
        "{%0,%1,%2,%3}, {%4,%5,%6,%7}, {%8,%9}, {%0,%1,%2,%3};"
        : "+f"(c[0]), "+f"(c[1]), "+f"(c[2]), "+f"(c[3])
        : "r"(a[0]), "r"(a[1]), "r"(a[2]), "r"(a[3]), "r"(b[0]), "r"(b[1]));
}

#define AS_STRIDE 20   // floats; bank = (4*row + k) % 32 for quad rows -> conflict-free frag loads
#define BS_STRIDE 136  // floats; bank = (8*k + n) % 32 -> conflict-free frag loads

template<int EPI>
__global__ __launch_bounds__(256) void mma_gemm(const float* __restrict__ A,
                                                const float* __restrict__ W,
                                                const float* __restrict__ bias,
                                                const float* __restrict__ res,
                                                float* __restrict__ out,
                                                int M, int N, int K) {
    __shared__ uint32_t As[128 * AS_STRIDE];   // [m][k] tf32 bits, 10.2 KB
    __shared__ uint32_t Bs[16 * BS_STRIDE];    // [k][n] tf32 bits,  8.7 KB

    int tid  = threadIdx.x;
    int wid  = tid >> 5, lane = tid & 31;
    int quad = lane >> 2, pos = lane & 3;
    int wm = (wid >> 2) * 64;     // warp m offset: 0 or 64
    int wn = (wid & 3) * 32;      // warp n offset: 0,32,64,96

    int bm = blockIdx.y * 128, bn = blockIdx.x * 128;

    float acc[4][4][4];
    #pragma unroll
    for (int i = 0; i < 4; i++)
        #pragma unroll
        for (int j = 0; j < 4; j++)
            #pragma unroll
            for (int r = 0; r < 4; r++) acc[i][j][r] = 0.f;

    // staging indices
    int ar  = tid >> 2;            // 0..63 (A rows; +64 for second half)
    int ak  = (tid & 3) * 4;       // 0,4,8,12
    int bk  = tid >> 5;            // 0..7 (B k rows; +8 for second half)
    int bn4 = (tid & 31) * 4;      // 0..124

    const float* Ap = A + (long)(bm + ar) * K + ak;
    const float* Wp = W + (long)bk * N + bn + bn4;

    // prefetch chunk 0
    float4 av0 = *(const float4*)(Ap);
    float4 av1 = *(const float4*)(Ap + (long)64 * K);
    float4 wv0 = *(const float4*)(Wp);
    float4 wv1 = *(const float4*)(Wp + (long)8 * N);

    for (int k0 = 0; k0 < K; k0 += 16) {
        // store current chunk to smem (convert to tf32 bits)
        {
            uint4 t;
            t.x = f2tf(av0.x); t.y = f2tf(av0.y); t.z = f2tf(av0.z); t.w = f2tf(av0.w);
            *(uint4*)&As[ar * AS_STRIDE + ak] = t;
            t.x = f2tf(av1.x); t.y = f2tf(av1.y); t.z = f2tf(av1.z); t.w = f2tf(av1.w);
            *(uint4*)&As[(ar + 64) * AS_STRIDE + ak] = t;
            t.x = f2tf(wv0.x); t.y = f2tf(wv0.y); t.z = f2tf(wv0.z); t.w = f2tf(wv0.w);
            *(uint4*)&Bs[bk * BS_STRIDE + bn4] = t;
            t.x = f2tf(wv1.x); t.y = f2tf(wv1.y); t.z = f2tf(wv1.z); t.w = f2tf(wv1.w);
            *(uint4*)&Bs[(bk + 8) * BS_STRIDE + bn4] = t;
        }
        __syncthreads();

        // prefetch next chunk while computing
        if (k0 + 16 < K) {
            Ap += 16;
            Wp += (long)16 * N;
            av0 = *(const float4*)(Ap);
            av1 = *(const float4*)(Ap + (long)64 * K);
            wv0 = *(const float4*)(Wp);
            wv1 = *(const float4*)(Wp + (long)8 * N);
        }

        #pragma unroll
        for (int ks = 0; ks < 16; ks += 8) {
            uint32_t af[4][4];
            #pragma unroll
            for (int i = 0; i < 4; i++) {
                int r = wm + i * 16 + quad;
                af[i][0] = As[r * AS_STRIDE + ks + pos];
                af[i][1] = As[(r + 8) * AS_STRIDE + ks + pos];
                af[i][2] = As[r * AS_STRIDE + ks + pos + 4];
                af[i][3] = As[(r + 8) * AS_STRIDE + ks + pos + 4];
            }
            uint32_t bf[4][2];
            #pragma unroll
            for (int j = 0; j < 4; j++) {
                int c = wn + j * 8 + quad;
                bf[j][0] = Bs[(ks + pos) * BS_STRIDE + c];
                bf[j][1] = Bs[(ks + pos + 4) * BS_STRIDE + c];
            }
            #pragma unroll
            for (int i = 0; i < 4; i++)
                #pragma unroll
                for (int j = 0; j < 4; j++)
                    mma_tf32(acc[i][j], af[i], bf[j]);
        }
        __syncthreads();
    }

    // epilogue
    #pragma unroll
    for (int i = 0; i < 4; i++) {
        #pragma unroll
        for (int j = 0; j < 4; j++) {
            int row0 = bm + wm + i * 16 + quad;
            int col0 = bn + wn + j * 8 + pos * 2;
            #pragma unroll
            for (int h = 0; h < 2; h++) {            // h=0: rows row0, h=1: row0+8
                int row = row0 + h * 8;
                float v0 = acc[i][j][2 * h + 0];
                float v1 = acc[i][j][2 * h + 1];
                long idx = (long)row * N + col0;
                if (EPI == 1) {
                    v0 = gelu_exact(v0 + bias[col0]);
                    v1 = gelu_exact(v1 + bias[col0 + 1]);
                } else { // EPI == 3
                    v0 += bias[col0]     + res[idx];
                    v1 += bias[col0 + 1] + res[idx + 1];
                }
                *(float2*)&out[idx] = make_float2(v0, v1);
            }
        }
    }
}

// ---------------- host launcher ---------------------------------------------
extern "C" void kernel_launch(void* const* d_in, const int* in_sizes, int n_in,
                              void* d_out, int out_size) {
    const float* x      = (const float*)d_in[0];
    const float* log_A  = (const float*)d_in[1];
    const float* Bm     = (const float*)d_in[2];
    const float* Cm     = (const float*)d_in[3];
    const float* Dv     = (const float*)d_in[4];
    const float* log_dt = (const float*)d_in[5];
    const float* gamma  = (const float*)d_in[6];
    const float* beta   = (const float*)d_in[7];
    const float* W1     = (const float*)d_in[8];
    const float* b1     = (const float*)d_in[9];
    const float* W2     = (const float*)d_in[10];
    const float* b2     = (const float*)d_in[11];
    float* out = (float*)d_out;

    float *xn, *xB, *hs, *y, *yn, *h1;
    cudaGetSymbolAddress((void**)&xn, g_xn);
    cudaGetSymbolAddress((void**)&xB, g_xB);
    cudaGetSymbolAddress((void**)&hs, g_hs);
    cudaGetSymbolAddress((void**)&y,  g_y);
    cudaGetSymbolAddress((void**)&yn, g_yn);
    cudaGetSymbolAddress((void**)&h1, g_h1);

    // 1. xn = LN(x)
    ln_kernel<<<MROWS, 256>>>(x, gamma, beta, xn);

    // 2. xB = xn @ B   [32768 x 64], K=512 (fp32)
    {
        dim3 grid(SDIM / 64, MROWS / 64);
        sgemm64<0><<<grid, 256>>>(xn, Bm, nullptr, nullptr, nullptr, nullptr,
                                  xB, MROWS, SDIM, DMODEL);
    }

    // 3. hs = scan(xB)
    scan_kernel<<<64, 256>>>(xB, log_A, log_dt, hs);

    // 4. y = hs @ C + x + xn*D   [32768 x 512], K=64 (fp32)
    {
        dim3 grid(DMODEL / 64, MROWS / 64);
        sgemm64<2><<<grid, 256>>>(hs, Cm, nullptr, x, xn, Dv,
                                  y, MROWS, DMODEL, SDIM);
    }

    // 5. yn = LN(y)
    ln_kernel<<<MROWS, 256>>>(y, gamma, beta, yn);

    // 6. h1 = gelu(yn @ W1 + b1)   [32768 x 1024], K=512 (tf32 MMA)
    {
        dim3 grid(HIDDEN / 128, MROWS / 128);
        mma_gemm<1><<<grid, 256>>>(yn, W1, b1, nullptr, h1,
                                   MROWS, HIDDEN, DMODEL);
    }

    // 7. out = y + h1 @ W2 + b2   [32768 x 512], K=1024 (tf32 MMA)
    {
        dim3 grid(DMODEL / 128, MROWS / 128);
        mma_gemm<3><<<grid, 256>>>(h1, W2, b2, y, out,
                                   MROWS, DMODEL, HIDDEN);
    }
}

// round 6
// speedup vs baseline: 1.3179x; 1.3179x over previous
#include <cuda_runtime.h>
#include <cuda_bf16.h>
#include <math.h>
#include <stdint.h>

#define BATCH 8
#define SEQLEN 4096
#define DMODEL 512
#define SDIM 64
#define MROWS (BATCH * SEQLEN)          // 32768
#define HIDDEN (2 * DMODEL)             // 1024

// ---------------- scratch (device globals; no allocation allowed) -----------
__device__ float g_xB[(long)MROWS * SDIM];     // 8 MB
__device__ float g_hs[(long)MROWS * SDIM];     // 8 MB
__device__ float g_y [(long)MROWS * DMODEL];   // 64 MB
__device__ float g_h1[(long)MROWS * HIDDEN];   // 128 MB
__device__ float g_mu1[MROWS], g_rs1[MROWS];
__device__ float g_mu2[MROWS], g_rs2[MROWS];
__device__ float g_cf[BATCH * SDIM * 32];      // chunk finals

// ---------------- LN stats: warp per row (512 cols) -------------------------
__global__ void ln_stats(const float* __restrict__ x,
                         float* __restrict__ mu, float* __restrict__ rstd) {
    int row  = blockIdx.x * 8 + (threadIdx.x >> 5);
    int lane = threadIdx.x & 31;
    const float4* xr = (const float4*)(x + (long)row * DMODEL);
    float s = 0.f, ss = 0.f;
    #pragma unroll
    for (int i = 0; i < 4; i++) {
        float4 v = xr[lane + 32 * i];
        s  += v.x + v.y + v.z + v.w;
        ss += v.x * v.x + v.y * v.y + v.z * v.z + v.w * v.w;
    }
    #pragma unroll
    for (int o = 16; o; o >>= 1) {
        s  += __shfl_xor_sync(0xffffffffu, s,  o);
        ss += __shfl_xor_sync(0xffffffffu, ss, o);
    }
    if (lane == 0) {
        float m = s * (1.0f / DMODEL);
        mu[row]   = m;
        rstd[row] = rsqrtf(ss * (1.0f / DMODEL) - m * m + 1e-5f);
    }
}

// ---------------- coalesced scan: pass 1 (local) -----------------------------
// xB/hs layout [b][l][s]; block = (chunk c, batch b), 64 threads = 64 states.
__global__ void scan_local(const float* __restrict__ xB,
                           const float* __restrict__ log_A,
                           const float* __restrict__ log_dt,
                           float* __restrict__ hs, float* __restrict__ cf) {
    int s = threadIdx.x, c = blockIdx.x, b = blockIdx.y;
    float a = expf(-expf(log_A[s]) * expf(log_dt[0]));
    long base = ((long)(b * SEQLEN + c * 128)) * SDIM + s;
    float h = 0.f;
    #pragma unroll 4
    for (int t = 0; t < 128; t++) {
        h = fmaf(a, h, xB[base + (long)t * SDIM]);
        hs[base + (long)t * SDIM] = h;
    }
    cf[((long)(b * SDIM + s)) * 32 + c] = h;
}

// ---------------- scan pass 2: carry fix-up ----------------------------------
__global__ void scan_fix(const float* __restrict__ cf,
                         const float* __restrict__ log_A,
                         const float* __restrict__ log_dt,
                         float* __restrict__ hs) {
    int s = threadIdx.x, c = blockIdx.x, b = blockIdx.y;
    if (c == 0) return;
    float a = expf(-expf(log_A[s]) * expf(log_dt[0]));
    float q = a;
    #pragma unroll
    for (int i = 0; i < 7; i++) q *= q;   // a^128
    const float* cfr = cf + ((long)(b * SDIM + s)) * 32;
    float carry = 0.f;
    for (int cc = 0; cc < c; cc++) carry = fmaf(carry, q, cfr[cc]);
    long base = ((long)(b * SEQLEN + c * 128)) * SDIM + s;
    float p = a;
    #pragma unroll 4
    for (int t = 0; t < 128; t++) {
        hs[base + (long)t * SDIM] = fmaf(carry, p, hs[base + (long)t * SDIM]);
        p *= a;
    }
}

// ---------------- tf32 MMA GEMM, pipelined ----------------------------------
// out = op(A) @ W + epilogue.  Block 128xBN, K-chunk 16, 8 warps (2m x 4n),
// warp tile 64 x (BN/4), m16n8k8 tf32 (raw fp32 bits -> HW truncation).
// LNF: A-side layernorm fused into staging ((a-mu)*rstd*gamma[k]+beta[k]).
// EPI 0: plain                   (xB = LN(x) @ B)
// EPI 1: gelu(acc + bias[n])     (h1)
// EPI 2: acc + x + LN1(x)*D[n]   (y)
// EPI 3: acc + bias[n] + res     (out)
__device__ __forceinline__ float gelu_exact(float v) {
    return 0.5f * v * (1.0f + erff(v * 0.70710678118654752f));
}
__device__ __forceinline__ void mma_tf32(float* c, const uint32_t* a, const uint32_t* b) {
    asm volatile(
        "mma.sync.aligned.m16n8k8.row.col.f32.tf32.tf32.f32 "
        "{%0,%1,%2,%3}, {%4,%5,%6,%7}, {%8,%9}, {%0,%1,%2,%3};"
        : "+f"(c[0]), "+f"(c[1]), "+f"(c[2]), "+f"(c[3])
        : "r"(a[0]), "r"(a[1]), "r"(a[2]), "r"(a[3]), "r"(b[0]), "r"(b[1]));
}
__device__ __forceinline__ void cp16(uint32_t dst, const void* src) {
    asm volatile("cp.async.cg.shared.global [%0], [%1], 16;" :: "r"(dst), "l"(src));
}

#define AS_STR 20   // bank = (20q+p)%32 all-distinct for frag reads

template<int EPI, int BN, bool LNF>
__global__ __launch_bounds__(256) void mma_gemm(
        const float* __restrict__ A, const float* __restrict__ W,
        const float* __restrict__ bias, const float* __restrict__ res,
        const float* __restrict__ dvec,
        const float* __restrict__ muA, const float* __restrict__ rsA,
        const float* __restrict__ muE, const float* __restrict__ rsE,
        const float* __restrict__ gamma, const float* __restrict__ beta,
        float* __restrict__ out, int M, int N, int K)
{
    constexpr int BSTR = (BN == 128) ? 136 : 72;  // bank = (8p+q)%32 distinct
    constexpr int WNW  = BN / 4;
    constexpr int NI   = WNW / 8;
    constexpr int BCP  = (16 * BN / 4) / 256;     // cp.async 16B units per thread

    __shared__ __align__(16) float As[2][128 * AS_STR];
    __shared__ __align__(16) float Bs[2][16 * BSTR];

    int tid = threadIdx.x, wid = tid >> 5, lane = tid & 31;
    int quad = lane >> 2, pos = lane & 3;
    int wm = (wid >> 2) * 64, wn = (wid & 3) * WNW;
    int bm = blockIdx.y * 128, bn = blockIdx.x * BN;

    float acc[4][NI][4];
    #pragma unroll
    for (int i = 0; i < 4; i++)
        #pragma unroll
        for (int j = 0; j < NI; j++)
            #pragma unroll
            for (int r = 0; r < 4; r++) acc[i][j][r] = 0.f;

    // A staging
    int ar = tid >> 2, ak = (tid & 3) * 4;
    const float* Ap = A + (long)(bm + ar) * K + ak;
    float mA0 = 0.f, rA0 = 1.f, mA1 = 0.f, rA1 = 1.f;
    if (LNF) {
        mA0 = muA[bm + ar];      rA0 = rsA[bm + ar];
        mA1 = muA[bm + ar + 64]; rA1 = rsA[bm + ar + 64];
    }
    float4 av0, av1;

    // ---- prologue: chunk 0 ----
    av0 = *(const float4*)(Ap);
    av1 = *(const float4*)(Ap + (long)64 * K);
    #pragma unroll
    for (int g = 0; g < BCP; g++) {
        int u = tid + g * 256;
        int r = u / (BN / 4), c4 = (u % (BN / 4)) * 4;
        uint32_t dst = (uint32_t)__cvta_generic_to_shared(&Bs[0][r * BSTR + c4]);
        cp16(dst, W + (long)r * N + bn + c4);
    }
    asm volatile("cp.async.commit_group;");
    {
        float4 t0 = av0, t1 = av1;
        if (LNF) {
            float4 g4 = *(const float4*)(gamma + ak);
            float4 b4 = *(const float4*)(beta  + ak);
            t0.x = (t0.x - mA0) * rA0 * g4.x + b4.x;
            t0.y = (t0.y - mA0) * rA0 * g4.y + b4.y;
            t0.z = (t0.z - mA0) * rA0 * g4.z + b4.z;
            t0.w = (t0.w - mA0) * rA0 * g4.w + b4.w;
            t1.x = (t1.x - mA1) * rA1 * g4.x + b4.x;
            t1.y = (t1.y - mA1) * rA1 * g4.y + b4.y;
            t1.z = (t1.z - mA1) * rA1 * g4.z + b4.z;
            t1.w = (t1.w - mA1) * rA1 * g4.w + b4.w;
        }
        *(float4*)&As[0][ar * AS_STR + ak]        = t0;
        *(float4*)&As[0][(ar + 64) * AS_STR + ak] = t1;
    }
    asm volatile("cp.async.wait_group 0;");
    __syncthreads();

    int buf = 0;
    for (int k0 = 0; k0 < K; k0 += 16) {
        bool more = (k0 + 16 < K);
        if (more) {
            av0 = *(const float4*)(Ap + k0 + 16);
            av1 = *(const float4*)(Ap + k0 + 16 + (long)64 * K);
            #pragma unroll
            for (int g = 0; g < BCP; g++) {
                int u = tid + g * 256;
                int r = u / (BN / 4), c4 = (u % (BN / 4)) * 4;
                uint32_t dst = (uint32_t)__cvta_generic_to_shared(&Bs[buf ^ 1][r * BSTR + c4]);
                cp16(dst, W + (long)(k0 + 16 + r) * N + bn + c4);
            }
            asm volatile("cp.async.commit_group;");
        }

        // compute on As[buf], Bs[buf]
        #pragma unroll
        for (int ks = 0; ks < 16; ks += 8) {
            uint32_t af[4][4];
            #pragma unroll
            for (int i = 0; i < 4; i++) {
                int r = wm + i * 16 + quad;
                af[i][0] = __float_as_uint(As[buf][r * AS_STR + ks + pos]);
                af[i][1] = __float_as_uint(As[buf][(r + 8) * AS_STR + ks + pos]);
                af[i][2] = __float_as_uint(As[buf][r * AS_STR + ks + pos + 4]);
                af[i][3] = __float_as_uint(As[buf][(r + 8) * AS_STR + ks + pos + 4]);
            }
            uint32_t bf[NI][2];
            #pragma unroll
            for (int j = 0; j < NI; j++) {
                int c = wn + j * 8 + quad;
                bf[j][0] = __float_as_uint(Bs[buf][(ks + pos) * BSTR + c]);
                bf[j][1] = __float_as_uint(Bs[buf][(ks + pos + 4) * BSTR + c]);
            }
            #pragma unroll
            for (int i = 0; i < 4; i++)
                #pragma unroll
                for (int j = 0; j < NI; j++)
                    mma_tf32(acc[i][j], af[i], bf[j]);
        }

        if (more) {
            float4 t0 = av0, t1 = av1;
            if (LNF) {
                float4 g4 = *(const float4*)(gamma + k0 + 16 + ak);
                float4 b4 = *(const float4*)(beta  + k0 + 16 + ak);
                t0.x = (t0.x - mA0) * rA0 * g4.x + b4.x;
                t0.y = (t0.y - mA0) * rA0 * g4.y + b4.y;
                t0.z = (t0.z - mA0) * rA0 * g4.z + b4.z;
                t0.w = (t0.w - mA0) * rA0 * g4.w + b4.w;
                t1.x = (t1.x - mA1) * rA1 * g4.x + b4.x;
                t1.y = (t1.y - mA1) * rA1 * g4.y + b4.y;
                t1.z = (t1.z - mA1) * rA1 * g4.z + b4.z;
                t1.w = (t1.w - mA1) * rA1 * g4.w + b4.w;
            }
            *(float4*)&As[buf ^ 1][ar * AS_STR + ak]        = t0;
            *(float4*)&As[buf ^ 1][(ar + 64) * AS_STR + ak] = t1;
            asm volatile("cp.async.wait_group 0;");
            __syncthreads();
        }
        buf ^= 1;
    }

    // ---- epilogue ----
    #pragma unroll
    for (int i = 0; i < 4; i++) {
        #pragma unroll
        for (int h = 0; h < 2; h++) {
            int row = bm + wm + i * 16 + quad + h * 8;
            float mur = 0.f, rsr = 1.f;
            if (EPI == 2) { mur = muE[row]; rsr = rsE[row]; }
            #pragma unroll
            for (int j = 0; j < NI; j++) {
                int col = bn + wn + j * 8 + pos * 2;
                float v0 = acc[i][j][2 * h + 0];
                float v1 = acc[i][j][2 * h + 1];
                long idx = (long)row * N + col;
                if (EPI == 1) {
                    v0 = gelu_exact(v0 + bias[col]);
                    v1 = gelu_exact(v1 + bias[col + 1]);
                } else if (EPI == 2) {
                    float x0 = res[idx], x1 = res[idx + 1];
                    float xn0 = (x0 - mur) * rsr * gamma[col]     + beta[col];
                    float xn1 = (x1 - mur) * rsr * gamma[col + 1] + beta[col + 1];
                    v0 += x0 + xn0 * dvec[col];
                    v1 += x1 + xn1 * dvec[col + 1];
                } else if (EPI == 3) {
                    v0 += bias[col]     + res[idx];
                    v1 += bias[col + 1] + res[idx + 1];
                }
                *(float2*)&out[idx] = make_float2(v0, v1);
            }
        }
    }
}

// ---------------- host launcher ---------------------------------------------
extern "C" void kernel_launch(void* const* d_in, const int* in_sizes, int n_in,
                              void* d_out, int out_size) {
    const float* x      = (const float*)d_in[0];
    const float* log_A  = (const float*)d_in[1];
    const float* Bm     = (const float*)d_in[2];
    const float* Cm     = (const float*)d_in[3];
    const float* Dv     = (const float*)d_in[4];
    const float* log_dt = (const float*)d_in[5];
    const float* gamma  = (const float*)d_in[6];
    const float* beta   = (const float*)d_in[7];
    const float* W1     = (const float*)d_in[8];
    const float* b1     = (const float*)d_in[9];
    const float* W2     = (const float*)d_in[10];
    const float* b2     = (const float*)d_in[11];
    float* out = (float*)d_out;

    float *xB, *hs, *y, *h1, *mu1, *rs1, *mu2, *rs2, *cf;
    cudaGetSymbolAddress((void**)&xB,  g_xB);
    cudaGetSymbolAddress((void**)&hs,  g_hs);
    cudaGetSymbolAddress((void**)&y,   g_y);
    cudaGetSymbolAddress((void**)&h1,  g_h1);
    cudaGetSymbolAddress((void**)&mu1, g_mu1);
    cudaGetSymbolAddress((void**)&rs1, g_rs1);
    cudaGetSymbolAddress((void**)&mu2, g_mu2);
    cudaGetSymbolAddress((void**)&rs2, g_rs2);
    cudaGetSymbolAddress((void**)&cf,  g_cf);

    // 1. LN1 stats on x
    ln_stats<<<MROWS / 8, 256>>>(x, mu1, rs1);

    // 2. xB = LN1(x) @ B   [32768 x 64], K=512, LN fused into A staging
    {
        dim3 grid(SDIM / 64, MROWS / 128);
        mma_gemm<0, 64, true><<<grid, 256>>>(
            x, Bm, nullptr, nullptr, nullptr,
            mu1, rs1, nullptr, nullptr, gamma, beta,
            xB, MROWS, SDIM, DMODEL);
    }

    // 3. hs = scan(xB)
    {
        dim3 grid(SEQLEN / 128, BATCH);
        scan_local<<<grid, 64>>>(xB, log_A, log_dt, hs, cf);
        scan_fix<<<grid, 64>>>(cf, log_A, log_dt, hs);
    }

    // 4. y = hs @ C + x + LN1(x)*D   [32768 x 512], K=64
    {
        dim3 grid(DMODEL / 128, MROWS / 128);
        mma_gemm<2, 128, false><<<grid, 256>>>(
            hs, Cm, nullptr, x, Dv,
            nullptr, nullptr, mu1, rs1, gamma, beta,
            y, MROWS, DMODEL, SDIM);
    }

    // 5. LN2 stats on y
    ln_stats<<<MROWS / 8, 256>>>(y, mu2, rs2);

    // 6. h1 = gelu(LN2(y) @ W1 + b1)   [32768 x 1024], K=512, LN fused
    {
        dim3 grid(HIDDEN / 128, MROWS / 128);
        mma_gemm<1, 128, true><<<grid, 256>>>(
            y, W1, b1, nullptr, nullptr,
            mu2, rs2, nullptr, nullptr, gamma, beta,
            h1, MROWS, HIDDEN, DMODEL);
    }

    // 7. out = y + h1 @ W2 + b2   [32768 x 512], K=1024
    {
        dim3 grid(DMODEL / 128, MROWS / 128);
        mma_gemm<3, 128, false><<<grid, 256>>>(
            h1, W2, b2, y, nullptr,
            nullptr, nullptr, nullptr, nullptr, gamma, beta,
            out, MROWS, DMODEL, HIDDEN);
    }
}